// round 4
// baseline (speedup 1.0000x reference)
#include <cuda_runtime.h>
#include <cuda_bf16.h>

// Problem constants (fixed by reference)
#define VOCAB      32000
#define EMBED_DIM  128
#define BATCH      32
#define MAX_TREES  512
#define NSEG       (BATCH * MAX_TREES)   // 16384

// Scratch: segment boundaries (device global — allocation-free)
__device__ int g_seg_start[NSEG + 1];

// ---------------------------------------------------------------------------
// Kernel 1: binary-search segment boundaries in the sorted tree_ids array.
// ---------------------------------------------------------------------------
__global__ void seg_bounds_kernel(const int* __restrict__ tree_ids, int n) {
    int s = blockIdx.x * blockDim.x + threadIdx.x;
    if (s > NSEG) return;
    int lo = 0, hi = n;
    while (lo < hi) {
        int mid = (lo + hi) >> 1;
        if (__ldg(&tree_ids[mid]) < s) lo = mid + 1;
        else hi = mid;
    }
    g_seg_start[s] = lo;
}

// ---------------------------------------------------------------------------
// Kernel 2: one warp per (segment, table). 32 lanes x float4 = full 128-float
// row per gather. Token ids for the NEXT 32-token chunk are prefetched while
// the current chunk's 32 row-gathers are issued, so the dependent id load
// never stalls the gather pipeline. 4 independent accumulators let 4 row
// loads be in flight per lane before any FADD dependency binds.
// ---------------------------------------------------------------------------
__global__ void __launch_bounds__(256)
seg_sum_kernel(const int*    __restrict__ token_ids,
               const float4* __restrict__ C_hop,    // [VOCAB][32] float4
               const float4* __restrict__ C_hop1,
               float4*       __restrict__ out,      // [2][NSEG][32] float4
               int n)
{
    const int gw   = (blockIdx.x * blockDim.x + threadIdx.x) >> 5;
    const int lane = threadIdx.x & 31;
    if (gw >= 2 * NSEG) return;

    const int seg = gw >> 1;
    const int tbl = gw & 1;
    const float4* __restrict__ C = tbl ? C_hop1 : C_hop;

    const int beg = g_seg_start[seg];
    const int end = g_seg_start[seg + 1];

    float4 a0 = make_float4(0.f, 0.f, 0.f, 0.f);
    float4 a1 = make_float4(0.f, 0.f, 0.f, 0.f);
    float4 a2 = make_float4(0.f, 0.f, 0.f, 0.f);
    float4 a3 = make_float4(0.f, 0.f, 0.f, 0.f);

    const int nm1   = n - 1;
    const int nfull = (end - beg) >> 5;   // full 32-token chunks

    int i = beg;
    // Prime: load chunk 0's ids (clamped so always in-bounds, branchless).
    int idx0 = beg + lane; if (idx0 > nm1) idx0 = nm1;
    int cur  = __ldg(&token_ids[idx0]);

    for (int c = 0; c < nfull; c++) {
        // Prefetch NEXT chunk's ids before touching this chunk's rows:
        // this load's ~250cyc latency overlaps the 32 row gathers below.
        int idxn = i + 32 + lane; if (idxn > nm1) idxn = nm1;
        const int nxt = __ldg(&token_ids[idxn]);

        #pragma unroll
        for (int u = 0; u < 32; u += 4) {
            int t0 = __shfl_sync(0xffffffffu, cur, u + 0);
            int t1 = __shfl_sync(0xffffffffu, cur, u + 1);
            int t2 = __shfl_sync(0xffffffffu, cur, u + 2);
            int t3 = __shfl_sync(0xffffffffu, cur, u + 3);
            float4 r0 = __ldcg(&C[t0 * 32 + lane]);
            float4 r1 = __ldcg(&C[t1 * 32 + lane]);
            float4 r2 = __ldcg(&C[t2 * 32 + lane]);
            float4 r3 = __ldcg(&C[t3 * 32 + lane]);
            a0.x += r0.x; a0.y += r0.y; a0.z += r0.z; a0.w += r0.w;
            a1.x += r1.x; a1.y += r1.y; a1.z += r1.z; a1.w += r1.w;
            a2.x += r2.x; a2.y += r2.y; a2.z += r2.z; a2.w += r2.w;
            a3.x += r3.x; a3.y += r3.y; a3.z += r3.z; a3.w += r3.w;
        }
        i += 32;
        cur = nxt;
    }

    // Remainder (< 32 tokens): ids already resident in `cur`.
    const int rem = end - i;
    for (int u = 0; u < rem; u++) {
        int t = __shfl_sync(0xffffffffu, cur, u);
        float4 r = __ldcg(&C[t * 32 + lane]);
        a0.x += r.x; a0.y += r.y; a0.z += r.z; a0.w += r.w;
    }

    a0.x += a1.x + a2.x + a3.x;
    a0.y += a1.y + a2.y + a3.y;
    a0.z += a1.z + a2.z + a3.z;
    a0.w += a1.w + a2.w + a3.w;

    // out layout: [2, NSEG, 32 float4]; key plane (tbl=0) first, then value.
    out[((size_t)tbl * NSEG + (size_t)seg) * 32 + lane] = a0;
}

// ---------------------------------------------------------------------------
// Launch
// ---------------------------------------------------------------------------
extern "C" void kernel_launch(void* const* d_in, const int* in_sizes, int n_in,
                              void* d_out, int out_size) {
    const int*    token_ids = (const int*)   d_in[0];
    const int*    tree_ids  = (const int*)   d_in[1];
    const float4* C_hop     = (const float4*)d_in[2];
    const float4* C_hop1    = (const float4*)d_in[3];
    float4*       out       = (float4*)      d_out;

    const int n = in_sizes[0];  // TOTAL_TOKENS

    // Kernel 1: segment boundaries (16385 binary searches)
    {
        int threads = 256;
        int blocks  = (NSEG + 1 + threads - 1) / threads;
        seg_bounds_kernel<<<blocks, threads>>>(tree_ids, n);
    }

    // Kernel 2: one warp per (segment, table) -> 32768 warps = 4096 blocks
    {
        int threads = 256;
        int blocks  = (2 * NSEG * 32 + threads - 1) / threads;  // 4096
        seg_sum_kernel<<<blocks, threads>>>(token_ids, C_hop, C_hop1, out, n);
    }
}

// round 6
// speedup vs baseline: 1.3567x; 1.3567x over previous
#include <cuda_runtime.h>
#include <cuda_fp16.h>

// Problem constants (fixed by reference)
#define VOCAB      32000
#define EMBED_DIM  128
#define BATCH      32
#define MAX_TREES  512
#define NSEG       (BATCH * MAX_TREES)   // 16384

// Scratch (allocation-free __device__ globals)
__device__ int g_seg_start[NSEG + 1];
// fp16 copies of both tables: 2 * 32000 * 128 * 2B = 16.4 MB.
// Viewed as u64 (8B = 4 halfs): each 128-half row = 32 u64, one per lane.
__device__ __align__(16) unsigned long long g_C16[2][VOCAB * EMBED_DIM / 4];

// ---------------------------------------------------------------------------
// Kernel 0: convert both f32 tables to fp16 scratch. 1,024,000 float4 reads
// per table; tables are L2-resident across graph replays (~48MB L2 traffic).
// ---------------------------------------------------------------------------
__global__ void __launch_bounds__(256)
convert_kernel(const float4* __restrict__ C_hop,
               const float4* __restrict__ C_hop1) {
    const int n4 = VOCAB * EMBED_DIM / 4;              // 1,024,000
    int i = blockIdx.x * blockDim.x + threadIdx.x;
    if (i >= n4) return;

    float4 a = __ldg(&C_hop[i]);
    float4 b = __ldg(&C_hop1[i]);

    union { __half2 h2[2]; unsigned long long u64; } ua, ub;
    ua.h2[0] = __floats2half2_rn(a.x, a.y);
    ua.h2[1] = __floats2half2_rn(a.z, a.w);
    ub.h2[0] = __floats2half2_rn(b.x, b.y);
    ub.h2[1] = __floats2half2_rn(b.z, b.w);

    g_C16[0][i] = ua.u64;
    g_C16[1][i] = ub.u64;
}

// ---------------------------------------------------------------------------
// Kernel 1: binary-search segment boundaries in the sorted tree_ids array.
// ---------------------------------------------------------------------------
__global__ void seg_bounds_kernel(const int* __restrict__ tree_ids, int n) {
    int s = blockIdx.x * blockDim.x + threadIdx.x;
    if (s > NSEG) return;
    int lo = 0, hi = n;
    while (lo < hi) {
        int mid = (lo + hi) >> 1;
        if (__ldg(&tree_ids[mid]) < s) lo = mid + 1;
        else hi = mid;
    }
    g_seg_start[s] = lo;
}

// ---------------------------------------------------------------------------
// Kernel 2: one warp per (segment, table). Row = 128 fp16 = 256B; each lane
// loads one 8B u64 (4 halfs) -> fully coalesced 256B per row gather. f32
// accumulation (4 independent accumulator sets for MLP). Ids fetched
// 32-at-a-time coalesced and shfl-distributed.
// ---------------------------------------------------------------------------
__global__ void __launch_bounds__(256)
seg_sum_kernel(const int* __restrict__ token_ids,
               float4*    __restrict__ out)        // [2][NSEG][32] float4
{
    const int gw   = (blockIdx.x * blockDim.x + threadIdx.x) >> 5;
    const int lane = threadIdx.x & 31;
    if (gw >= 2 * NSEG) return;

    const int seg = gw >> 1;
    const int tbl = gw & 1;
    const unsigned long long* __restrict__ T = g_C16[tbl];

    const int beg = g_seg_start[seg];
    const int end = g_seg_start[seg + 1];

    float4 a0 = make_float4(0.f, 0.f, 0.f, 0.f);
    float4 a1 = make_float4(0.f, 0.f, 0.f, 0.f);
    float4 a2 = make_float4(0.f, 0.f, 0.f, 0.f);
    float4 a3 = make_float4(0.f, 0.f, 0.f, 0.f);

    int base = beg;
    for (; base + 32 <= end; base += 32) {
        const int myid = __ldg(&token_ids[base + lane]);
        #pragma unroll
        for (int u = 0; u < 32; u += 4) {
            int t0 = __shfl_sync(0xffffffffu, myid, u + 0);
            int t1 = __shfl_sync(0xffffffffu, myid, u + 1);
            int t2 = __shfl_sync(0xffffffffu, myid, u + 2);
            int t3 = __shfl_sync(0xffffffffu, myid, u + 3);
            unsigned long long r0 = __ldcg(&T[t0 * 32 + lane]);
            unsigned long long r1 = __ldcg(&T[t1 * 32 + lane]);
            unsigned long long r2 = __ldcg(&T[t2 * 32 + lane]);
            unsigned long long r3 = __ldcg(&T[t3 * 32 + lane]);

            union { unsigned long long u; __half2 h[2]; } c0, c1, c2, c3;
            c0.u = r0; c1.u = r1; c2.u = r2; c3.u = r3;

            float2 f;
            f = __half22float2(c0.h[0]); a0.x += f.x; a0.y += f.y;
            f = __half22float2(c0.h[1]); a0.z += f.x; a0.w += f.y;
            f = __half22float2(c1.h[0]); a1.x += f.x; a1.y += f.y;
            f = __half22float2(c1.h[1]); a1.z += f.x; a1.w += f.y;
            f = __half22float2(c2.h[0]); a2.x += f.x; a2.y += f.y;
            f = __half22float2(c2.h[1]); a2.z += f.x; a2.w += f.y;
            f = __half22float2(c3.h[0]); a3.x += f.x; a3.y += f.y;
            f = __half22float2(c3.h[1]); a3.z += f.x; a3.w += f.y;
        }
    }
    // Remainder (< 32 tokens)
    if (base < end) {
        const int rem  = end - base;
        const int myid = (lane < rem) ? __ldg(&token_ids[base + lane]) : 0;
        for (int u = 0; u < rem; u++) {
            int t = __shfl_sync(0xffffffffu, myid, u);
            unsigned long long r = __ldcg(&T[t * 32 + lane]);
            union { unsigned long long u; __half2 h[2]; } c;
            c.u = r;
            float2 f;
            f = __half22float2(c.h[0]); a0.x += f.x; a0.y += f.y;
            f = __half22float2(c.h[1]); a0.z += f.x; a0.w += f.y;
        }
    }

    a0.x += a1.x + a2.x + a3.x;
    a0.y += a1.y + a2.y + a3.y;
    a0.z += a1.z + a2.z + a3.z;
    a0.w += a1.w + a2.w + a3.w;

    // Lane owns output floats [4*lane, 4*lane+4) of its 128-float row.
    out[((size_t)tbl * NSEG + (size_t)seg) * 32 + lane] = a0;
}

// ---------------------------------------------------------------------------
// Launch
// ---------------------------------------------------------------------------
extern "C" void kernel_launch(void* const* d_in, const int* in_sizes, int n_in,
                              void* d_out, int out_size) {
    const int*    token_ids = (const int*)   d_in[0];
    const int*    tree_ids  = (const int*)   d_in[1];
    const float4* C_hop     = (const float4*)d_in[2];
    const float4* C_hop1    = (const float4*)d_in[3];
    float4*       out       = (float4*)      d_out;

    const int n = in_sizes[0];  // TOTAL_TOKENS

    // Kernel 0: f32 -> fp16 table conversion (1,024,000 float4s per table)
    {
        int threads = 256;
        int blocks  = (VOCAB * EMBED_DIM / 4 + threads - 1) / threads;  // 4000
        convert_kernel<<<blocks, threads>>>(C_hop, C_hop1);
    }

    // Kernel 1: segment boundaries (16385 binary searches)
    {
        int threads = 256;
        int blocks  = (NSEG + 1 + threads - 1) / threads;
        seg_bounds_kernel<<<blocks, threads>>>(tree_ids, n);
    }

    // Kernel 2: one warp per (segment, table) -> 32768 warps = 4096 blocks
    {
        int threads = 256;
        int blocks  = (2 * NSEG * 32 + threads - 1) / threads;  // 4096
        seg_sum_kernel<<<blocks, threads>>>(token_ids, out);
    }
}

// round 7
// speedup vs baseline: 1.5013x; 1.1065x over previous
#include <cuda_runtime.h>
#include <cuda_fp16.h>

// Problem constants (fixed by reference)
#define VOCAB      32000
#define EMBED_DIM  128
#define BATCH      32
#define MAX_TREES  512
#define NSEG       (BATCH * MAX_TREES)   // 16384

// Scratch (allocation-free __device__ globals)
__device__ int g_seg_start[NSEG + 1];
// Packed interleaved fp16 tables: per token, 512B record =
//   [128 fp16 key row | 128 fp16 value row] = 32 uint4 (lane l owns uint4 l).
// Total: 32000 * 512B = 16.4 MB.
__device__ __align__(16) uint4 g_pack[VOCAB * 32];

// ---------------------------------------------------------------------------
// Kernel 0: convert both f32 tables into the packed fp16 layout.
// Thread k handles 8 floats of key + 8 floats of value for token k/16.
// ---------------------------------------------------------------------------
__global__ void __launch_bounds__(256)
convert_kernel(const float4* __restrict__ C_hop,
               const float4* __restrict__ C_hop1) {
    const int NT = VOCAB * 16;                 // 512,000 threads
    int k = blockIdx.x * blockDim.x + threadIdx.x;
    if (k >= NT) return;
    const int r = k >> 4;        // token row
    const int c = k & 15;        // uint4 chunk within the 256B half-record

    float4 a0 = __ldg(&C_hop [r * 32 + 2 * c]);
    float4 a1 = __ldg(&C_hop [r * 32 + 2 * c + 1]);
    float4 b0 = __ldg(&C_hop1[r * 32 + 2 * c]);
    float4 b1 = __ldg(&C_hop1[r * 32 + 2 * c + 1]);

    union { __half2 h2[4]; uint4 u; } pk, pv;
    pk.h2[0] = __floats2half2_rn(a0.x, a0.y);
    pk.h2[1] = __floats2half2_rn(a0.z, a0.w);
    pk.h2[2] = __floats2half2_rn(a1.x, a1.y);
    pk.h2[3] = __floats2half2_rn(a1.z, a1.w);
    pv.h2[0] = __floats2half2_rn(b0.x, b0.y);
    pv.h2[1] = __floats2half2_rn(b0.z, b0.w);
    pv.h2[2] = __floats2half2_rn(b1.x, b1.y);
    pv.h2[3] = __floats2half2_rn(b1.z, b1.w);

    g_pack[r * 32 + c]      = pk.u;   // key half  (lanes 0-15 read this)
    g_pack[r * 32 + 16 + c] = pv.u;   // value half (lanes 16-31)
}

// ---------------------------------------------------------------------------
// Kernel 1: binary-search segment boundaries in the sorted tree_ids array.
// ---------------------------------------------------------------------------
__global__ void seg_bounds_kernel(const int* __restrict__ tree_ids, int n) {
    int s = blockIdx.x * blockDim.x + threadIdx.x;
    if (s > NSEG) return;
    int lo = 0, hi = n;
    while (lo < hi) {
        int mid = (lo + hi) >> 1;
        if (__ldg(&tree_ids[mid]) < s) lo = mid + 1;
        else hi = mid;
    }
    g_seg_start[s] = lo;
}

// ---------------------------------------------------------------------------
// Kernel 2: ONE warp per segment. One 512B warp load per token fetches BOTH
// tables (lanes 0-15: key row, lanes 16-31: value row; uint4 = 8 fp16 each).
// f32 accumulation, 2 independent accumulator sets, ids coalesced 32-at-a-
// time + shuffle. Halves warp-level load instructions vs per-table warps.
// ---------------------------------------------------------------------------
__device__ __forceinline__ void acc8(float4& sa, float4& sb, uint4 r) {
    union { uint4 u; __half2 h[4]; } c; c.u = r;
    float2 f;
    f = __half22float2(c.h[0]); sa.x += f.x; sa.y += f.y;
    f = __half22float2(c.h[1]); sa.z += f.x; sa.w += f.y;
    f = __half22float2(c.h[2]); sb.x += f.x; sb.y += f.y;
    f = __half22float2(c.h[3]); sb.z += f.x; sb.w += f.y;
}

__global__ void __launch_bounds__(256)
seg_sum_kernel(const int* __restrict__ token_ids,
               float4*    __restrict__ out)        // [2][NSEG][32] float4
{
    const int seg  = (blockIdx.x * blockDim.x + threadIdx.x) >> 5;
    const int lane = threadIdx.x & 31;
    if (seg >= NSEG) return;

    const int beg = g_seg_start[seg];
    const int end = g_seg_start[seg + 1];

    float4 s0a = make_float4(0.f,0.f,0.f,0.f), s0b = make_float4(0.f,0.f,0.f,0.f);
    float4 s1a = make_float4(0.f,0.f,0.f,0.f), s1b = make_float4(0.f,0.f,0.f,0.f);

    int base = beg;
    for (; base + 32 <= end; base += 32) {
        const int myid = __ldg(&token_ids[base + lane]);
        #pragma unroll
        for (int u = 0; u < 32; u += 4) {
            int t0 = __shfl_sync(0xffffffffu, myid, u + 0);
            int t1 = __shfl_sync(0xffffffffu, myid, u + 1);
            int t2 = __shfl_sync(0xffffffffu, myid, u + 2);
            int t3 = __shfl_sync(0xffffffffu, myid, u + 3);
            uint4 r0 = __ldcg(&g_pack[t0 * 32 + lane]);
            uint4 r1 = __ldcg(&g_pack[t1 * 32 + lane]);
            uint4 r2 = __ldcg(&g_pack[t2 * 32 + lane]);
            uint4 r3 = __ldcg(&g_pack[t3 * 32 + lane]);
            acc8(s0a, s0b, r0);
            acc8(s1a, s1b, r1);
            acc8(s0a, s0b, r2);
            acc8(s1a, s1b, r3);
        }
    }
    // Remainder (< 32 tokens)
    if (base < end) {
        const int rem  = end - base;
        const int myid = (lane < rem) ? __ldg(&token_ids[base + lane]) : 0;
        for (int u = 0; u < rem; u++) {
            int t = __shfl_sync(0xffffffffu, myid, u);
            uint4 r = __ldcg(&g_pack[t * 32 + lane]);
            acc8(s0a, s0b, r);
        }
    }

    s0a.x += s1a.x; s0a.y += s1a.y; s0a.z += s1a.z; s0a.w += s1a.w;
    s0b.x += s1b.x; s0b.y += s1b.y; s0b.z += s1b.z; s0b.w += s1b.w;

    // lanes 0-15 hold key-row floats [8c..8c+8); lanes 16-31 value-row.
    const int tbl = lane >> 4;          // 0 = key, 1 = value
    const int col = lane & 15;          // uint4-pair index within the row
    float4* dst = &out[(((size_t)tbl * NSEG) + seg) * 32 + col * 2];
    dst[0] = s0a;
    dst[1] = s0b;
}

// ---------------------------------------------------------------------------
// Launch
// ---------------------------------------------------------------------------
extern "C" void kernel_launch(void* const* d_in, const int* in_sizes, int n_in,
                              void* d_out, int out_size) {
    const int*    token_ids = (const int*)   d_in[0];
    const int*    tree_ids  = (const int*)   d_in[1];
    const float4* C_hop     = (const float4*)d_in[2];
    const float4* C_hop1    = (const float4*)d_in[3];
    float4*       out       = (float4*)      d_out;

    const int n = in_sizes[0];  // TOTAL_TOKENS

    // Kernel 0: f32 -> packed fp16 conversion (512,000 threads)
    {
        int threads = 256;
        int blocks  = (VOCAB * 16 + threads - 1) / threads;   // 2000
        convert_kernel<<<blocks, threads>>>(C_hop, C_hop1);
    }

    // Kernel 1: segment boundaries (16385 binary searches)
    {
        int threads = 256;
        int blocks  = (NSEG + 1 + threads - 1) / threads;
        seg_bounds_kernel<<<blocks, threads>>>(tree_ids, n);
    }

    // Kernel 2: one warp per segment -> 16384 warps = 2048 blocks
    {
        int threads = 256;
        int blocks  = (NSEG * 32 + threads - 1) / threads;    // 2048
        seg_sum_kernel<<<blocks, threads>>>(token_ids, out);
    }
}